// round 1
// baseline (speedup 1.0000x reference)
#include <cuda_runtime.h>
#include <cstdint>

#define N_USERS 50000
#define N_ITEMS 100000
#define N_NODES (N_USERS + N_ITEMS)
#define D 64
#define EPS 1e-6f

// Scratch (allocation-free): emb (current), embn (scatter target), acc (sum of layer outputs)
__device__ float g_emb [N_NODES * D];
__device__ float g_embn[N_NODES * D];
__device__ float g_acc [N_NODES * D];
__device__ int   g_is64;   // 1 if index arrays are int64, 0 if int32

// ---------------------------------------------------------------------------
// Detect index dtype: if the buffer is int32-backed, reading int64s yields
// huge values (hi word = next int32, almost surely nonzero). Check 64 values.
// ---------------------------------------------------------------------------
__global__ void detect_kernel(const void* rows, int n) {
    if (blockIdx.x == 0 && threadIdx.x == 0) {
        const long long* p = (const long long*)rows;
        int ok = 1;
        int lim = (n < 64) ? n : 64;
        for (int i = 0; i < lim; i++) {
            long long v = p[i];
            if (v < 0 || v >= (long long)N_NODES) { ok = 0; break; }
        }
        g_is64 = ok;
    }
}

__device__ __forceinline__ long long load_idx(const void* p, int e) {
    if (g_is64) return ((const long long*)p)[e];
    return (long long)((const int*)p)[e];
}

// ---------------------------------------------------------------------------
// Init: emb = concat(user_emb, item_emb); acc = emb; embn = 0. float4 vectorized.
// ---------------------------------------------------------------------------
__global__ void init_kernel(const float* __restrict__ user_emb,
                            const float* __restrict__ item_emb) {
    int i = blockIdx.x * blockDim.x + threadIdx.x;   // float4 index
    const int total4 = N_NODES * D / 4;
    if (i >= total4) return;
    const int usplit = N_USERS * D / 4;
    float4 v;
    if (i < usplit) v = ((const float4*)user_emb)[i];
    else            v = ((const float4*)item_emb)[i - usplit];
    ((float4*)g_emb)[i] = v;
    ((float4*)g_acc)[i] = v;
    ((float4*)g_embn)[i] = make_float4(0.f, 0.f, 0.f, 0.f);
}

// ---------------------------------------------------------------------------
// SpMM scatter: embn[row] += val * emb[col].  16 threads per edge, each owns
// one float4 slice of the 64-d row; vector red.global.add.v4.f32 (sm_90+).
// ---------------------------------------------------------------------------
__global__ void spmm_kernel(const float* __restrict__ vals,
                            const void* __restrict__ rows,
                            const void* __restrict__ cols,
                            int n_edges) {
    long long tid = (long long)blockIdx.x * blockDim.x + threadIdx.x;
    int e = (int)(tid >> 4);
    int t = (int)(tid & 15);
    if (e >= n_edges) return;

    long long r = load_idx(rows, e);
    long long c = load_idx(cols, e);
    float v = vals[e];

    float4 m = ((const float4*)(g_emb + c * D))[t];
    m.x *= v; m.y *= v; m.z *= v; m.w *= v;

    float* dst = g_embn + r * D + t * 4;
    asm volatile("red.global.add.v4.f32 [%0], {%1,%2,%3,%4};"
                 :: "l"(dst), "f"(m.x), "f"(m.y), "f"(m.z), "f"(m.w)
                 : "memory");
}

// ---------------------------------------------------------------------------
// Combine: per-node growth gating, emb update, acc accumulate, and re-zero
// embn for the next layer. One warp per node, float2 per lane.
// ---------------------------------------------------------------------------
__global__ void combine_kernel() {
    int node = blockIdx.x * (blockDim.x >> 5) + (threadIdx.x >> 5);
    int lane = threadIdx.x & 31;
    if (node >= N_NODES) return;

    float2* eptr = (float2*)(g_emb  + (long long)node * D);
    float2* nptr = (float2*)(g_embn + (long long)node * D);
    float2* aptr = (float2*)(g_acc  + (long long)node * D);

    float2 o = eptr[lane];
    float2 nn = nptr[lane];

    float dx = o.x - nn.x + EPS;
    float dy = o.y - nn.y + EPS;
    float s = dx * dx + dy * dy;
    #pragma unroll
    for (int off = 16; off; off >>= 1)
        s += __shfl_xor_sync(0xFFFFFFFFu, s, off);

    float osn   = sqrtf(s);
    float dnew  = log1pf(osn);
    float inv   = 1.0f / (1.0f + dnew);
    float w_old = inv;
    float w_new = dnew * inv;

    float2 r;
    r.x = w_old * o.x + w_new * nn.x;
    r.y = w_old * o.y + w_new * nn.y;
    eptr[lane] = r;

    float2 a = aptr[lane];
    a.x += r.x; a.y += r.y;
    aptr[lane] = a;

    nptr[lane] = make_float2(0.f, 0.f);   // ready for next layer's scatter
}

// ---------------------------------------------------------------------------
// Gather: out[0:1024] = acc[user_id]/4, out[1024:2048] = acc[N_USERS+item_id]/4
// One warp per output row.
// ---------------------------------------------------------------------------
__global__ void gather_kernel(const void* __restrict__ user_id,
                              const void* __restrict__ item_id,
                              float* __restrict__ out,
                              int n_ids) {
    int i = blockIdx.x * (blockDim.x >> 5) + (threadIdx.x >> 5);
    int lane = threadIdx.x & 31;
    if (i >= 2 * n_ids) return;

    long long node;
    if (i < n_ids) node = load_idx(user_id, i);
    else           node = (long long)N_USERS + load_idx(item_id, i - n_ids);

    float2 a = ((const float2*)(g_acc + node * D))[lane];
    ((float2*)(out + (long long)i * D))[lane] = make_float2(a.x * 0.25f, a.y * 0.25f);
}

// ---------------------------------------------------------------------------
// kernel_launch
// inputs: 0 user_emb [50000,64] f32, 1 item_emb [100000,64] f32,
//         2 adj_vals [E] f32, 3 adj_rows [E] int, 4 adj_cols [E] int,
//         5 user_id [1024] int, 6 item_id [1024] int
// out: [2048, 64] f32 (u_embed then i_embed)
// ---------------------------------------------------------------------------
extern "C" void kernel_launch(void* const* d_in, const int* in_sizes, int n_in,
                              void* d_out, int out_size) {
    const float* user_emb = (const float*)d_in[0];
    const float* item_emb = (const float*)d_in[1];
    const float* adj_vals = (const float*)d_in[2];
    const void*  adj_rows = d_in[3];
    const void*  adj_cols = d_in[4];
    const void*  user_id  = d_in[5];
    const void*  item_id  = d_in[6];
    float* out = (float*)d_out;

    int n_edges = in_sizes[3];
    int n_ids   = in_sizes[5];

    detect_kernel<<<1, 32>>>(adj_rows, n_edges);

    {
        int total4 = N_NODES * D / 4;
        init_kernel<<<(total4 + 255) / 256, 256>>>(user_emb, item_emb);
    }

    long long spmm_threads = (long long)n_edges * 16;
    int spmm_blocks = (int)((spmm_threads + 255) / 256);
    int comb_blocks = (N_NODES + 7) / 8;   // 8 warps (nodes) per 256-thread block

    for (int layer = 0; layer < 3; layer++) {
        spmm_kernel<<<spmm_blocks, 256>>>(adj_vals, adj_rows, adj_cols, n_edges);
        combine_kernel<<<comb_blocks, 256>>>();
    }

    int gather_rows = 2 * n_ids;
    gather_kernel<<<(gather_rows + 7) / 8, 256>>>(user_id, item_id, out, n_ids);
}

// round 3
// speedup vs baseline: 2.0848x; 2.0848x over previous
#include <cuda_runtime.h>
#include <cstdint>

#define N_USERS 50000
#define N_ITEMS 100000
#define N_NODES (N_USERS + N_ITEMS)
#define D 64
#define EPS 1e-6f
#define E_MAX 2400000
#define SCAN_BLOCK 1024
#define MAX_SCAN_BLOCKS ((N_NODES + SCAN_BLOCK - 1) / SCAN_BLOCK)

// ---------------------------------------------------------------------------
// Static scratch (allocation-free per harness rules).
// NOTE: device symbols are ONLY referenced from device code — passing them as
// host-side kernel arguments silently passes the host shadow address (ATS!).
// ---------------------------------------------------------------------------
__device__ float g_embs[4][N_NODES * D];       // layer 0..3 embeddings
__device__ int   g_cnt[N_NODES];               // per-row edge counts
__device__ int   g_incl[N_NODES];              // per-block inclusive scan
__device__ int   g_blk[MAX_SCAN_BLOCKS];       // block sums -> block offsets
__device__ int   g_row_ptr[N_NODES + 1];       // CSR row pointers
__device__ int   g_row_fill[N_NODES];          // atomic cursors for scatter
__device__ int   g_csr_col[E_MAX];             // CSR column indices
__device__ float g_csr_val[E_MAX];             // CSR values
__device__ int   g_is64;                       // index dtype flag

// ---------------------------------------------------------------------------
// Index dtype detection (int64 vs int32)
// ---------------------------------------------------------------------------
__global__ void detect_kernel(const void* rows, int n) {
    if (blockIdx.x == 0 && threadIdx.x == 0) {
        const long long* p = (const long long*)rows;
        int ok = 1;
        int lim = (n < 64) ? n : 64;
        for (int i = 0; i < lim; i++) {
            long long v = p[i];
            if (v < 0 || v >= (long long)N_NODES) { ok = 0; break; }
        }
        g_is64 = ok;
    }
}

__device__ __forceinline__ int load_idx(const void* p, int e) {
    if (g_is64) return (int)((const long long*)p)[e];
    return ((const int*)p)[e];
}

// ---------------------------------------------------------------------------
// CSR build
// ---------------------------------------------------------------------------
__global__ void zero_cnt_kernel() {
    int i = blockIdx.x * blockDim.x + threadIdx.x;
    if (i < N_NODES) g_cnt[i] = 0;
}

__global__ void hist_kernel(const void* __restrict__ rows, int n_edges) {
    int e = blockIdx.x * blockDim.x + threadIdx.x;
    if (e >= n_edges) return;
    atomicAdd(&g_cnt[load_idx(rows, e)], 1);
}

// Inclusive scan within blocks of SCAN_BLOCK, Hillis-Steele.
__global__ void scan1_kernel() {
    __shared__ int sh[SCAN_BLOCK];
    int i = blockIdx.x * SCAN_BLOCK + threadIdx.x;
    int v = (i < N_NODES) ? g_cnt[i] : 0;
    sh[threadIdx.x] = v;
    __syncthreads();
    #pragma unroll
    for (int off = 1; off < SCAN_BLOCK; off <<= 1) {
        int t = (threadIdx.x >= off) ? sh[threadIdx.x - off] : 0;
        __syncthreads();
        sh[threadIdx.x] += t;
        __syncthreads();
    }
    if (i < N_NODES) g_incl[i] = sh[threadIdx.x];
    if (threadIdx.x == SCAN_BLOCK - 1) g_blk[blockIdx.x] = sh[threadIdx.x];
}

// Serial exclusive scan over ~147 block sums.
__global__ void scan2_kernel(int nb) {
    if (blockIdx.x == 0 && threadIdx.x == 0) {
        int run = 0;
        for (int i = 0; i < nb; i++) { int t = g_blk[i]; g_blk[i] = run; run += t; }
    }
}

// row_ptr[i] = exclusive prefix; row_ptr[N] = total; init cursors.
__global__ void scan3_kernel() {
    int i = blockIdx.x * blockDim.x + threadIdx.x;
    if (i >= N_NODES) return;
    int inc = g_incl[i] + g_blk[i / SCAN_BLOCK];
    int exc = inc - g_cnt[i];
    g_row_ptr[i] = exc;
    g_row_fill[i] = exc;
    if (i == N_NODES - 1) g_row_ptr[N_NODES] = inc;
}

__global__ void scatter_kernel(const void* __restrict__ rows,
                               const void* __restrict__ cols,
                               const float* __restrict__ vals,
                               int n_edges) {
    int e = blockIdx.x * blockDim.x + threadIdx.x;
    if (e >= n_edges) return;
    int r = load_idx(rows, e);
    int c = load_idx(cols, e);
    float v = vals[e];
    int pos = atomicAdd(&g_row_fill[r], 1);
    g_csr_col[pos] = c;
    g_csr_val[pos] = v;
}

// ---------------------------------------------------------------------------
// Init: g_embs[0] = concat(user_emb, item_emb)
// ---------------------------------------------------------------------------
__global__ void init_kernel(const float* __restrict__ user_emb,
                            const float* __restrict__ item_emb) {
    int i = blockIdx.x * blockDim.x + threadIdx.x;   // float4 index
    const int total4 = N_NODES * D / 4;
    if (i >= total4) return;
    const int usplit = N_USERS * D / 4;
    float4 v = (i < usplit) ? ((const float4*)user_emb)[i]
                            : ((const float4*)item_emb)[i - usplit];
    ((float4*)g_embs[0])[i] = v;
}

// ---------------------------------------------------------------------------
// Fused layer: per-node CSR gather-sum + growth gating + write next layer.
// One warp per node; each lane owns a float2 slice. Layer index passed as int
// so device-symbol addressing stays in device code.
// ---------------------------------------------------------------------------
__global__ void layer_kernel(int l) {
    int node = blockIdx.x * (blockDim.x >> 5) + (threadIdx.x >> 5);
    int lane = threadIdx.x & 31;
    if (node >= N_NODES) return;

    const float2* base = (const float2*)g_embs[l];
    float2*       outp = (float2*)g_embs[l + 1];

    int beg = __ldg(&g_row_ptr[node]);
    int end = __ldg(&g_row_ptr[node + 1]);

    float2 acc = make_float2(0.f, 0.f);

    int i = beg;
    for (; i + 1 < end; i += 2) {            // 2-way unroll for MLP
        int   c0 = __ldg(&g_csr_col[i]);
        int   c1 = __ldg(&g_csr_col[i + 1]);
        float v0 = __ldg(&g_csr_val[i]);
        float v1 = __ldg(&g_csr_val[i + 1]);
        float2 x0 = base[c0 * 32 + lane];
        float2 x1 = base[c1 * 32 + lane];
        acc.x += v0 * x0.x + v1 * x1.x;
        acc.y += v0 * x0.y + v1 * x1.y;
    }
    if (i < end) {
        int   c = __ldg(&g_csr_col[i]);
        float v = __ldg(&g_csr_val[i]);
        float2 x = base[c * 32 + lane];
        acc.x += v * x.x;
        acc.y += v * x.y;
    }

    float2 o = base[node * 32 + lane];

    float dx = o.x - acc.x + EPS;
    float dy = o.y - acc.y + EPS;
    float s = dx * dx + dy * dy;
    #pragma unroll
    for (int off = 16; off; off >>= 1)
        s += __shfl_xor_sync(0xFFFFFFFFu, s, off);

    float osn   = sqrtf(s);
    float dnew  = log1pf(osn);
    float inv   = 1.0f / (1.0f + dnew);
    float w_old = inv;
    float w_new = dnew * inv;

    float2 r;
    r.x = w_old * o.x + w_new * acc.x;
    r.y = w_old * o.y + w_new * acc.y;
    outp[node * 32 + lane] = r;
}

// ---------------------------------------------------------------------------
// Gather: out row = mean over the 4 layer embeddings of the selected node.
// ---------------------------------------------------------------------------
__global__ void gather_kernel(const void* __restrict__ user_id,
                              const void* __restrict__ item_id,
                              float* __restrict__ out,
                              int n_ids) {
    int i = blockIdx.x * (blockDim.x >> 5) + (threadIdx.x >> 5);
    int lane = threadIdx.x & 31;
    if (i >= 2 * n_ids) return;

    int node;
    if (i < n_ids) node = load_idx(user_id, i);
    else           node = N_USERS + load_idx(item_id, i - n_ids);

    int off = node * 32 + lane;
    float2 a0 = ((const float2*)g_embs[0])[off];
    float2 a1 = ((const float2*)g_embs[1])[off];
    float2 a2 = ((const float2*)g_embs[2])[off];
    float2 a3 = ((const float2*)g_embs[3])[off];
    float2 r;
    r.x = (a0.x + a1.x + a2.x + a3.x) * 0.25f;
    r.y = (a0.y + a1.y + a2.y + a3.y) * 0.25f;
    ((float2*)(out + (long long)i * D))[lane] = r;
}

// ---------------------------------------------------------------------------
// kernel_launch
// ---------------------------------------------------------------------------
extern "C" void kernel_launch(void* const* d_in, const int* in_sizes, int n_in,
                              void* d_out, int out_size) {
    const float* user_emb = (const float*)d_in[0];
    const float* item_emb = (const float*)d_in[1];
    const float* adj_vals = (const float*)d_in[2];
    const void*  adj_rows = d_in[3];
    const void*  adj_cols = d_in[4];
    const void*  user_id  = d_in[5];
    const void*  item_id  = d_in[6];
    float* out = (float*)d_out;

    int n_edges = in_sizes[3];
    if (n_edges > E_MAX) n_edges = E_MAX;
    int n_ids = in_sizes[5];

    detect_kernel<<<1, 32>>>(adj_rows, n_edges);

    // CSR build
    zero_cnt_kernel<<<(N_NODES + 255) / 256, 256>>>();
    hist_kernel<<<(n_edges + 255) / 256, 256>>>(adj_rows, n_edges);
    int nb = (N_NODES + SCAN_BLOCK - 1) / SCAN_BLOCK;
    scan1_kernel<<<nb, SCAN_BLOCK>>>();
    scan2_kernel<<<1, 32>>>(nb);
    scan3_kernel<<<(N_NODES + 255) / 256, 256>>>();
    scatter_kernel<<<(n_edges + 255) / 256, 256>>>(adj_rows, adj_cols, adj_vals, n_edges);

    // emb0
    {
        int total4 = N_NODES * D / 4;
        init_kernel<<<(total4 + 255) / 256, 256>>>(user_emb, item_emb);
    }

    // 3 fused layers: warp per node, 8 nodes per 256-thread block
    int layer_blocks = (N_NODES + 7) / 8;
    layer_kernel<<<layer_blocks, 256>>>(0);
    layer_kernel<<<layer_blocks, 256>>>(1);
    layer_kernel<<<layer_blocks, 256>>>(2);

    // final gather + mean
    int gather_rows = 2 * n_ids;
    gather_kernel<<<(gather_rows + 7) / 8, 256>>>(user_id, item_id, out, n_ids);
}